// round 15
// baseline (speedup 1.0000x reference)
#include <cuda_runtime.h>
#include <math.h>

#define HD 64
#define NMAX 100000
#define EMAX 1600000

// ---------------- device scratch (no allocations allowed) ----------------
__device__ __align__(16) float gAggr[NMAX * HD];
__device__ __align__(16) float gH[NMAX * HD];
__device__ __align__(16) float gU[65 * HD];   // piecewise-linear slope table
__device__ __align__(16) float gV[65 * HD];   // piecewise-linear offset table
__device__ float gS[HD];                      // sorted breakpoints
__device__ int gIs64;                         // edge_index dtype flag
__device__ __align__(16) uint4 gRec[EMAX];    // dst-sorted edge records {src, a, lo, -}
__device__ int gCnt[NMAX];
__device__ int gFill[NMAX];
__device__ int gOff[NMAX + 1];
__device__ int gPart[256];

// ---------------- f32x2 packed helpers ----------------
static __device__ __forceinline__ unsigned long long pk2(float a, float b) {
    unsigned long long r;
    asm("mov.b64 %0, {%1, %2};" : "=l"(r) : "f"(a), "f"(b));
    return r;
}
static __device__ __forceinline__ void upk2(unsigned long long v, float& a, float& b) {
    asm("mov.b64 {%0, %1}, %2;" : "=f"(a), "=f"(b) : "l"(v));
}
static __device__ __forceinline__ unsigned long long ffma2(
    unsigned long long a, unsigned long long b, unsigned long long c) {
    unsigned long long d;
    asm("fma.rn.f32x2 %0, %1, %2, %3;" : "=l"(d) : "l"(a), "l"(b), "l"(c));
    return d;
}

// ---------------- prep: piecewise-linear edge-MLP tables (parallel over 17 blocks) ----------------
__global__ void prep_kernel(const float* __restrict__ w1, const float* __restrict__ b1,
                            const float* __restrict__ w2, const float* __restrict__ b2) {
    __shared__ float sw1[64], sb1[64], st[64], ss[64], stp[65];
    __shared__ float sw2[4096];
    int tid = threadIdx.x;
    if (tid < 64) { sw1[tid] = w1[tid]; sb1[tid] = b1[tid]; }
    for (int i = tid; i < 4096; i += 256) sw2[i] = w2[i];
    __syncthreads();
    if (tid < 64) {
        float w = sw1[tid], b = sb1[tid];
        st[tid] = (w != 0.0f) ? (-b / w) : __int_as_float(0x7f800000);
    }
    __syncthreads();
    if (tid < 64) {  // rank sort
        float v = st[tid];
        int rank = 0;
        for (int k = 0; k < 64; k++) {
            float u = st[k];
            rank += (u < v) || (u == v && k < tid);
        }
        ss[rank] = v;
    }
    __syncthreads();
    if (tid <= 64) {
        float lo = (tid == 0) ? -__int_as_float(0x7f800000) : ss[tid - 1];
        float hi = (tid == 64) ? __int_as_float(0x7f800000) : ss[tid];
        bool loI = !(lo > -3.0e38f);
        bool hiI = !(hi < 3.0e38f);
        float tp;
        if (loI && hiI)      tp = 0.0f;
        else if (loI)        tp = hi - 1.0f;
        else if (hiI)        tp = lo + 1.0f;
        else                 tp = 0.5f * lo + 0.5f * hi;
        stp[tid] = tp;
        if (blockIdx.x == 0 && tid < 64) gS[tid] = ss[tid];
    }
    __syncthreads();
    int idx = blockIdx.x * 256 + tid;
    if (idx < 65 * 64) {
        int i = idx >> 6, k = idx & 63;
        float a = stp[i];
        float U = 0.f, V = 0.f;
        for (int j = 0; j < 64; j++) {
            float w = sw1[j], b = sb1[j];
            if (a * w + b > 0.0f) {
                float wk = sw2[j * 64 + k];
                U = fmaf(w, wk, U);
                V = fmaf(b, wk, V);
            }
        }
        gU[idx] = U;
        gV[idx] = V + __ldg(b2 + k);
    }
}

// ---------------- sniff: int64 vs int32 edge_index ----------------
__global__ void sniff_kernel(const int* __restrict__ p, long long E) {
    __shared__ int nz;
    if (threadIdx.x == 0) nz = 0;
    __syncthreads();
    long long lim = 1024;
    if (E / 2 < lim) lim = E / 2;
    for (long long i = threadIdx.x; i < lim; i += blockDim.x)
        if (p[2 * i + 1] != 0) atomicOr(&nz, 1);
    __syncthreads();
    if (threadIdx.x == 0) gIs64 = (nz == 0) ? 1 : 0;
}

// ---------------- counting sort by dst ----------------
__global__ void zero_int_kernel(int n) {
    int i = blockIdx.x * blockDim.x + threadIdx.x;
    if (i < n) { gCnt[i] = 0; gFill[i] = 0; }
}

__global__ void hist_kernel(const void* __restrict__ idxPtr, long long E) {
    const int is64 = gIs64;
    const long long* i64 = (const long long*)idxPtr;
    const int* i32 = (const int*)idxPtr;
    long long stride = (long long)gridDim.x * blockDim.x;
    for (long long e = (long long)blockIdx.x * blockDim.x + threadIdx.x; e < E; e += stride) {
        int dst = is64 ? (int)i64[E + e] : i32[E + e];
        atomicAdd(&gCnt[dst], 1);
    }
}

__global__ void scan1_kernel(int n) {
    __shared__ int sd[256];
    int base = blockIdx.x * 512;
    int i0 = base + threadIdx.x, i1 = base + 256 + threadIdx.x;
    int c = 0;
    if (i0 < n) c += gCnt[i0];
    if (i1 < n) c += gCnt[i1];
    sd[threadIdx.x] = c;
    __syncthreads();
    for (int s = 128; s > 0; s >>= 1) {
        if (threadIdx.x < s) sd[threadIdx.x] += sd[threadIdx.x + s];
        __syncthreads();
    }
    if (threadIdx.x == 0) gPart[blockIdx.x] = sd[0];
}

__global__ void scan2_kernel(int nb) {
    __shared__ int sd[256];
    int tid = threadIdx.x;
    int v = (tid < nb) ? gPart[tid] : 0;
    sd[tid] = v;
    __syncthreads();
    for (int ofs = 1; ofs < 256; ofs <<= 1) {
        int add = 0;
        if (tid >= ofs) add = sd[tid - ofs];
        __syncthreads();
        sd[tid] += add;
        __syncthreads();
    }
    if (tid < nb) gPart[tid] = sd[tid] - v;  // exclusive
}

__global__ void scan3_kernel(int n) {
    __shared__ int sd[256];
    int base = blockIdx.x * 512;
    int i0 = base + 2 * threadIdx.x, i1 = i0 + 1;
    int c0 = (i0 < n) ? gCnt[i0] : 0;
    int c1 = (i1 < n) ? gCnt[i1] : 0;
    int tsum = c0 + c1;
    sd[threadIdx.x] = tsum;
    __syncthreads();
    for (int ofs = 1; ofs < 256; ofs <<= 1) {
        int add = 0;
        if (threadIdx.x >= ofs) add = sd[threadIdx.x - ofs];
        __syncthreads();
        sd[threadIdx.x] += add;
        __syncthreads();
    }
    int ex = gPart[blockIdx.x] + sd[threadIdx.x] - tsum;
    if (i0 < n) gOff[i0] = ex;
    if (i1 < n) gOff[i1] = ex + c0;
    if (i0 == n - 1) gOff[n] = ex + c0;
    if (i1 == n - 1) gOff[n] = ex + c0 + c1;
}

__global__ void scatter_kernel(const void* __restrict__ idxPtr,
                               const float* __restrict__ attr, long long E) {
    __shared__ float sS[64];
    if (threadIdx.x < 64) sS[threadIdx.x] = gS[threadIdx.x];
    __syncthreads();
    const int is64 = gIs64;
    const long long* i64 = (const long long*)idxPtr;
    const int* i32 = (const int*)idxPtr;
    long long stride = (long long)gridDim.x * blockDim.x;
    for (long long e = (long long)blockIdx.x * blockDim.x + threadIdx.x; e < E; e += stride) {
        int src, dst;
        if (is64) { src = (int)i64[e]; dst = (int)i64[E + e]; }
        else      { src = i32[e];      dst = i32[E + e]; }
        float a = __ldg(attr + e);
        int lo = 0, hi = 64;
#pragma unroll
        for (int it = 0; it < 7; it++) {
            if (lo < hi) {
                int mid = (lo + hi) >> 1;
                if (sS[mid] < a) lo = mid + 1; else hi = mid;
            }
        }
        int pos = gOff[dst] + atomicAdd(&gFill[dst], 1);
        gRec[pos] = make_uint4((unsigned)src, __float_as_uint(a), (unsigned)lo, 0u);
    }
}

// ---------------- CSR aggregation: no atomics, register accumulate ----------------
// 16 lanes per dst (one float4 chunk each), 2 dsts per warp.
__global__ void __launch_bounds__(256) edge_aggr_kernel(
    const float* __restrict__ hin, float* __restrict__ aggr, int n) {
    __shared__ float4 sU[65 * 16];
    __shared__ float4 sV[65 * 16];
    const float4* gU4 = (const float4*)gU;
    const float4* gV4 = (const float4*)gV;
    for (int i = threadIdx.x; i < 65 * 16; i += 256) { sU[i] = gU4[i]; sV[i] = gV4[i]; }
    __syncthreads();

    const int lane = threadIdx.x & 31;
    const int sub = lane >> 4;
    const int c = lane & 15;

    long long w = ((long long)blockIdx.x * 256 + threadIdx.x) >> 5;
    long long nw = ((long long)gridDim.x * 256) >> 5;
    for (long long d = w * 2 + sub; d < n; d += nw * 2) {
        int e = __ldg(&gOff[d]);
        int en = __ldg(&gOff[d + 1]);
        float4 acc = make_float4(0.f, 0.f, 0.f, 0.f);
        for (; e + 1 < en; e += 2) {  // 2-way unroll: two independent gather chains
            uint4 r0 = __ldg(&gRec[e]);
            uint4 r1 = __ldg(&gRec[e + 1]);
            float a0 = __uint_as_float(r0.y), a1 = __uint_as_float(r1.y);
            float4 u0 = sU[r0.z * 16 + c], v0 = sV[r0.z * 16 + c];
            float4 u1 = sU[r1.z * 16 + c], v1 = sV[r1.z * 16 + c];
            float4 h0 = __ldg((const float4*)(hin + ((size_t)r0.x << 6)) + c);
            float4 h1 = __ldg((const float4*)(hin + ((size_t)r1.x << 6)) + c);
            acc.x += fmaxf(fmaf(a0, u0.x, v0.x) + h0.x, 0.f) + fmaxf(fmaf(a1, u1.x, v1.x) + h1.x, 0.f);
            acc.y += fmaxf(fmaf(a0, u0.y, v0.y) + h0.y, 0.f) + fmaxf(fmaf(a1, u1.y, v1.y) + h1.y, 0.f);
            acc.z += fmaxf(fmaf(a0, u0.z, v0.z) + h0.z, 0.f) + fmaxf(fmaf(a1, u1.z, v1.z) + h1.z, 0.f);
            acc.w += fmaxf(fmaf(a0, u0.w, v0.w) + h0.w, 0.f) + fmaxf(fmaf(a1, u1.w, v1.w) + h1.w, 0.f);
        }
        if (e < en) {
            uint4 r0 = __ldg(&gRec[e]);
            float a0 = __uint_as_float(r0.y);
            float4 u0 = sU[r0.z * 16 + c], v0 = sV[r0.z * 16 + c];
            float4 h0 = __ldg((const float4*)(hin + ((size_t)r0.x << 6)) + c);
            acc.x += fmaxf(fmaf(a0, u0.x, v0.x) + h0.x, 0.f);
            acc.y += fmaxf(fmaf(a0, u0.y, v0.y) + h0.y, 0.f);
            acc.z += fmaxf(fmaf(a0, u0.z, v0.z) + h0.z, 0.f);
            acc.w += fmaxf(fmaf(a0, u0.w, v0.w) + h0.w, 0.f);
        }
        ((float4*)(aggr + ((size_t)d << 6)))[c] = acc;
    }
}

// ---------------- fused conv MLP: out = relu( relu(z@W1+b1) @ W2 + b2 ), z=(1+eps)x+aggr ----------------
__global__ void __launch_bounds__(128) conv_mlp_kernel(
    const float* X, const float* Ag, const float* __restrict__ epsPtr,
    const float* __restrict__ W1, const float* __restrict__ B1,
    const float* __restrict__ W2, const float* __restrict__ B2,
    float* Out, int n) {
    __shared__ __align__(16) float sW1[4096];
    __shared__ __align__(16) float sW2[4096];
    __shared__ float sB1[64], sB2[64];
    for (int i = threadIdx.x; i < 4096; i += 128) { sW1[i] = W1[i]; sW2[i] = W2[i]; }
    if (threadIdx.x < 64) { sB1[threadIdx.x] = B1[threadIdx.x]; sB2[threadIdx.x] = B2[threadIdx.x]; }
    __syncthreads();
    int r = blockIdx.x * 128 + threadIdx.x;
    if (r >= n) return;
    float ep = 1.0f + __ldg(epsPtr);

    unsigned long long acc[32];
#pragma unroll
    for (int p = 0; p < 32; p++) acc[p] = pk2(sB1[2 * p], sB1[2 * p + 1]);

    const float4* x4 = (const float4*)(X + ((size_t)r << 6));
    const float4* y4 = (const float4*)(Ag + ((size_t)r << 6));
#pragma unroll 1
    for (int jc = 0; jc < 16; jc++) {
        float4 xv = __ldg(x4 + jc), yv = __ldg(y4 + jc);
        float zz[4];
        zz[0] = fmaf(ep, xv.x, yv.x);
        zz[1] = fmaf(ep, xv.y, yv.y);
        zz[2] = fmaf(ep, xv.z, yv.z);
        zz[3] = fmaf(ep, xv.w, yv.w);
#pragma unroll
        for (int jj = 0; jj < 4; jj++) {
            unsigned long long zb = pk2(zz[jj], zz[jj]);
            const ulonglong2* wr = (const ulonglong2*)(sW1 + ((4 * jc + jj) << 6));
#pragma unroll
            for (int q = 0; q < 16; q++) {
                ulonglong2 wv = wr[q];
                acc[2 * q]     = ffma2(zb, wv.x, acc[2 * q]);
                acc[2 * q + 1] = ffma2(zb, wv.y, acc[2 * q + 1]);
            }
        }
    }

    unsigned long long acc2[32];
#pragma unroll
    for (int p = 0; p < 32; p++) acc2[p] = pk2(sB2[2 * p], sB2[2 * p + 1]);
#pragma unroll
    for (int p = 0; p < 32; p++) {
        float t0, t1;
        upk2(acc[p], t0, t1);
        t0 = fmaxf(t0, 0.f);
        t1 = fmaxf(t1, 0.f);
        unsigned long long zb0 = pk2(t0, t0);
        unsigned long long zb1 = pk2(t1, t1);
        const ulonglong2* w0 = (const ulonglong2*)(sW2 + ((2 * p) << 6));
        const ulonglong2* w1r = (const ulonglong2*)(sW2 + ((2 * p + 1) << 6));
#pragma unroll
        for (int q = 0; q < 16; q++) {
            ulonglong2 wv = w0[q];
            acc2[2 * q]     = ffma2(zb0, wv.x, acc2[2 * q]);
            acc2[2 * q + 1] = ffma2(zb0, wv.y, acc2[2 * q + 1]);
        }
#pragma unroll
        for (int q = 0; q < 16; q++) {
            ulonglong2 wv = w1r[q];
            acc2[2 * q]     = ffma2(zb1, wv.x, acc2[2 * q]);
            acc2[2 * q + 1] = ffma2(zb1, wv.y, acc2[2 * q + 1]);
        }
    }
    float4* o4 = (float4*)(Out + ((size_t)r << 6));
#pragma unroll
    for (int q = 0; q < 16; q++) {
        float a, b, cc, dd;
        upk2(acc2[2 * q], a, b);
        upk2(acc2[2 * q + 1], cc, dd);
        o4[q] = make_float4(fmaxf(a, 0.f), fmaxf(b, 0.f), fmaxf(cc, 0.f), fmaxf(dd, 0.f));
    }
}

// ---------------- classifier + fused log_softmax (H=64 -> C=40) ----------------
__global__ void __launch_bounds__(256) cls_kernel(
    const float* __restrict__ X, const float* __restrict__ W,
    const float* __restrict__ Bv, float* __restrict__ Out, int n) {
    __shared__ __align__(16) float sW[64 * 40];
    __shared__ float sB[40];
    for (int i = threadIdx.x; i < 64 * 40; i += 256) sW[i] = W[i];
    if (threadIdx.x < 40) sB[threadIdx.x] = Bv[threadIdx.x];
    __syncthreads();
    int r = blockIdx.x * 256 + threadIdx.x;
    if (r >= n) return;
    float4 acc[10];
#pragma unroll
    for (int q = 0; q < 10; q++)
        acc[q] = make_float4(sB[4 * q], sB[4 * q + 1], sB[4 * q + 2], sB[4 * q + 3]);
    const float4* x4 = (const float4*)(X + ((size_t)r << 6));
#pragma unroll 1
    for (int jc = 0; jc < 16; jc++) {
        float4 xv = __ldg(x4 + jc);
        float xs[4] = {xv.x, xv.y, xv.z, xv.w};
#pragma unroll
        for (int jj = 0; jj < 4; jj++) {
            float xj = xs[jj];
            const float4* wr = (const float4*)(sW + (4 * jc + jj) * 40);
#pragma unroll
            for (int q = 0; q < 10; q++) {
                float4 wv = wr[q];
                acc[q].x = fmaf(xj, wv.x, acc[q].x);
                acc[q].y = fmaf(xj, wv.y, acc[q].y);
                acc[q].z = fmaf(xj, wv.z, acc[q].z);
                acc[q].w = fmaf(xj, wv.w, acc[q].w);
            }
        }
    }
    float m = -3.4e38f;
#pragma unroll
    for (int q = 0; q < 10; q++)
        m = fmaxf(m, fmaxf(fmaxf(acc[q].x, acc[q].y), fmaxf(acc[q].z, acc[q].w)));
    float s = 0.f;
#pragma unroll
    for (int q = 0; q < 10; q++)
        s += expf(acc[q].x - m) + expf(acc[q].y - m) + expf(acc[q].z - m) + expf(acc[q].w - m);
    float lse = m + logf(s);
    float4* o4 = (float4*)(Out + (size_t)r * 40);
#pragma unroll
    for (int q = 0; q < 10; q++)
        o4[q] = make_float4(acc[q].x - lse, acc[q].y - lse, acc[q].z - lse, acc[q].w - lse);
}

// ---------------- launch ----------------
extern "C" void kernel_launch(void* const* d_in, const int* in_sizes, int n_in,
                              void* d_out, int out_size) {
    const float* x     = (const float*)d_in[0];
    const void*  eidx  = d_in[1];
    const float* eattr = (const float*)d_in[2];
    const float* e_w1  = (const float*)d_in[3];
    const float* e_b1  = (const float*)d_in[4];
    const float* e_w2  = (const float*)d_in[5];
    const float* e_b2  = (const float*)d_in[6];
    const float* eps1  = (const float*)d_in[7];
    const float* m1_w1 = (const float*)d_in[8];
    const float* m1_b1 = (const float*)d_in[9];
    const float* m1_w2 = (const float*)d_in[10];
    const float* m1_b2 = (const float*)d_in[11];
    const float* eps2  = (const float*)d_in[12];
    const float* m2_w1 = (const float*)d_in[13];
    const float* m2_b1 = (const float*)d_in[14];
    const float* m2_w2 = (const float*)d_in[15];
    const float* m2_b2 = (const float*)d_in[16];
    const float* lin_w = (const float*)d_in[17];
    const float* lin_b = (const float*)d_in[18];

    int N = in_sizes[0] / HD;
    long long E = in_sizes[2];
    float* out = (float*)d_out;

    void *pA, *pH;
    cudaGetSymbolAddress(&pA, gAggr);
    cudaGetSymbolAddress(&pH, gH);
    float* A = (float*)pA;
    float* H = (float*)pH;

    int nbScan = (N + 511) / 512;
    int nbMlp = (N + 127) / 128;
    int nbCls = (N + 255) / 256;

    // --- one-time preprocessing (tables + dst-sorted edge records) ---
    prep_kernel<<<17, 256>>>(e_w1, e_b1, e_w2, e_b2);
    sniff_kernel<<<1, 256>>>((const int*)eidx, E);
    zero_int_kernel<<<(N + 255) / 256, 256>>>(N);
    hist_kernel<<<1184, 256>>>(eidx, E);
    scan1_kernel<<<nbScan, 256>>>(N);
    scan2_kernel<<<1, 256>>>(nbScan);
    scan3_kernel<<<nbScan, 256>>>(N);
    scatter_kernel<<<1184, 256>>>(eidx, eattr, E);

    // --- conv1 ---
    edge_aggr_kernel<<<1184, 256>>>(x, A, N);
    conv_mlp_kernel<<<nbMlp, 128>>>(x, A, eps1, m1_w1, m1_b1, m1_w2, m1_b2, H, N);

    // --- conv2 (MLP in-place on H) ---
    edge_aggr_kernel<<<1184, 256>>>(H, A, N);
    conv_mlp_kernel<<<nbMlp, 128>>>(H, A, eps2, m2_w1, m2_b1, m2_w2, m2_b2, H, N);

    // --- classifier + log_softmax ---
    cls_kernel<<<nbCls, 256>>>(H, lin_w, lin_b, out, N);
}

// round 16
// speedup vs baseline: 1.0667x; 1.0667x over previous
#include <cuda_runtime.h>
#include <math.h>

#define HD 64
#define NMAX 100000
#define EMAX 1600000

// ---------------- device scratch (no allocations allowed) ----------------
__device__ __align__(16) float gAggr[NMAX * HD];
__device__ __align__(16) float gH[NMAX * HD];
__device__ __align__(16) float gU[65 * HD];   // piecewise-linear slope table
__device__ __align__(16) float gV[65 * HD];   // piecewise-linear offset table
__device__ float gS[HD];                      // sorted breakpoints
__device__ int gIs64;                         // edge_index dtype flag
__device__ __align__(16) uint2 gRec[EMAX];    // dst-sorted records {src|lo<<20, a}
__device__ int gRank[EMAX];                   // rank of edge within its dst segment
__device__ int gCnt[NMAX];
__device__ int gOff[NMAX + 1];
__device__ int gPart[256];

// ---------------- f32x2 packed helpers ----------------
static __device__ __forceinline__ unsigned long long pk2(float a, float b) {
    unsigned long long r;
    asm("mov.b64 %0, {%1, %2};" : "=l"(r) : "f"(a), "f"(b));
    return r;
}
static __device__ __forceinline__ void upk2(unsigned long long v, float& a, float& b) {
    asm("mov.b64 {%0, %1}, %2;" : "=f"(a), "=f"(b) : "l"(v));
}
static __device__ __forceinline__ unsigned long long ffma2(
    unsigned long long a, unsigned long long b, unsigned long long c) {
    unsigned long long d;
    asm("fma.rn.f32x2 %0, %1, %2, %3;" : "=l"(d) : "l"(a), "l"(b), "l"(c));
    return d;
}

// ---------------- prep: piecewise-linear edge-MLP tables ----------------
__global__ void prep_kernel(const float* __restrict__ w1, const float* __restrict__ b1,
                            const float* __restrict__ w2, const float* __restrict__ b2) {
    __shared__ float sw1[64], sb1[64], st[64], ss[64], stp[65];
    __shared__ float sw2[4096];
    int tid = threadIdx.x;
    if (tid < 64) { sw1[tid] = w1[tid]; sb1[tid] = b1[tid]; }
    for (int i = tid; i < 4096; i += 256) sw2[i] = w2[i];
    __syncthreads();
    if (tid < 64) {
        float w = sw1[tid], b = sb1[tid];
        st[tid] = (w != 0.0f) ? (-b / w) : __int_as_float(0x7f800000);
    }
    __syncthreads();
    if (tid < 64) {  // rank sort
        float v = st[tid];
        int rank = 0;
        for (int k = 0; k < 64; k++) {
            float u = st[k];
            rank += (u < v) || (u == v && k < tid);
        }
        ss[rank] = v;
    }
    __syncthreads();
    if (tid <= 64) {
        float lo = (tid == 0) ? -__int_as_float(0x7f800000) : ss[tid - 1];
        float hi = (tid == 64) ? __int_as_float(0x7f800000) : ss[tid];
        bool loI = !(lo > -3.0e38f);
        bool hiI = !(hi < 3.0e38f);
        float tp;
        if (loI && hiI)      tp = 0.0f;
        else if (loI)        tp = hi - 1.0f;
        else if (hiI)        tp = lo + 1.0f;
        else                 tp = 0.5f * lo + 0.5f * hi;
        stp[tid] = tp;
        if (blockIdx.x == 0 && tid < 64) gS[tid] = ss[tid];
    }
    __syncthreads();
    int idx = blockIdx.x * 256 + tid;
    if (idx < 65 * 64) {
        int i = idx >> 6, k = idx & 63;
        float a = stp[i];
        float U = 0.f, V = 0.f;
        for (int j = 0; j < 64; j++) {
            float w = sw1[j], b = sb1[j];
            if (a * w + b > 0.0f) {
                float wk = sw2[j * 64 + k];
                U = fmaf(w, wk, U);
                V = fmaf(b, wk, V);
            }
        }
        gU[idx] = U;
        gV[idx] = V + __ldg(b2 + k);
    }
}

// ---------------- sniff: int64 vs int32 edge_index ----------------
__global__ void sniff_kernel(const int* __restrict__ p, long long E) {
    __shared__ int nz;
    if (threadIdx.x == 0) nz = 0;
    __syncthreads();
    long long lim = 1024;
    if (E / 2 < lim) lim = E / 2;
    for (long long i = threadIdx.x; i < lim; i += blockDim.x)
        if (p[2 * i + 1] != 0) atomicOr(&nz, 1);
    __syncthreads();
    if (threadIdx.x == 0) gIs64 = (nz == 0) ? 1 : 0;
}

// ---------------- counting sort by dst ----------------
__global__ void zero_int_kernel(int n) {
    int i = blockIdx.x * blockDim.x + threadIdx.x;
    if (i < n) gCnt[i] = 0;
}

// histogram; atomicAdd return value = rank of this edge within its dst segment
__global__ void hist_kernel(const void* __restrict__ idxPtr, long long E) {
    const int is64 = gIs64;
    const long long* i64 = (const long long*)idxPtr;
    const int* i32 = (const int*)idxPtr;
    long long stride = (long long)gridDim.x * blockDim.x;
    for (long long e = (long long)blockIdx.x * blockDim.x + threadIdx.x; e < E; e += stride) {
        int dst = is64 ? (int)__ldg(&i64[E + e]) : __ldg(&i32[E + e]);
        gRank[e] = atomicAdd(&gCnt[dst], 1);
    }
}

__global__ void scan1_kernel(int n) {
    __shared__ int sd[256];
    int base = blockIdx.x * 512;
    int i0 = base + threadIdx.x, i1 = base + 256 + threadIdx.x;
    int c = 0;
    if (i0 < n) c += gCnt[i0];
    if (i1 < n) c += gCnt[i1];
    sd[threadIdx.x] = c;
    __syncthreads();
    for (int s = 128; s > 0; s >>= 1) {
        if (threadIdx.x < s) sd[threadIdx.x] += sd[threadIdx.x + s];
        __syncthreads();
    }
    if (threadIdx.x == 0) gPart[blockIdx.x] = sd[0];
}

__global__ void scan2_kernel(int nb) {
    __shared__ int sd[256];
    int tid = threadIdx.x;
    int v = (tid < nb) ? gPart[tid] : 0;
    sd[tid] = v;
    __syncthreads();
    for (int ofs = 1; ofs < 256; ofs <<= 1) {
        int add = 0;
        if (tid >= ofs) add = sd[tid - ofs];
        __syncthreads();
        sd[tid] += add;
        __syncthreads();
    }
    if (tid < nb) gPart[tid] = sd[tid] - v;  // exclusive
}

__global__ void scan3_kernel(int n) {
    __shared__ int sd[256];
    int base = blockIdx.x * 512;
    int i0 = base + 2 * threadIdx.x, i1 = i0 + 1;
    int c0 = (i0 < n) ? gCnt[i0] : 0;
    int c1 = (i1 < n) ? gCnt[i1] : 0;
    int tsum = c0 + c1;
    sd[threadIdx.x] = tsum;
    __syncthreads();
    for (int ofs = 1; ofs < 256; ofs <<= 1) {
        int add = 0;
        if (threadIdx.x >= ofs) add = sd[threadIdx.x - ofs];
        __syncthreads();
        sd[threadIdx.x] += add;
        __syncthreads();
    }
    int ex = gPart[blockIdx.x] + sd[threadIdx.x] - tsum;
    if (i0 < n) gOff[i0] = ex;
    if (i1 < n) gOff[i1] = ex + c0;
    if (i0 == n - 1) gOff[n] = ex + c0;
    if (i1 == n - 1) gOff[n] = ex + c0 + c1;
}

// atomic-free scatter: pos = gOff[dst] + precomputed rank; 8-byte packed record
__global__ void scatter_kernel(const void* __restrict__ idxPtr,
                               const float* __restrict__ attr, long long E) {
    __shared__ float sS[64];
    if (threadIdx.x < 64) sS[threadIdx.x] = gS[threadIdx.x];
    __syncthreads();
    const int is64 = gIs64;
    const long long* i64 = (const long long*)idxPtr;
    const int* i32 = (const int*)idxPtr;
    long long stride = (long long)gridDim.x * blockDim.x;
    for (long long e = (long long)blockIdx.x * blockDim.x + threadIdx.x; e < E; e += stride) {
        int src, dst;
        if (is64) { src = (int)__ldg(&i64[e]); dst = (int)__ldg(&i64[E + e]); }
        else      { src = __ldg(&i32[e]);      dst = __ldg(&i32[E + e]); }
        float a = __ldg(attr + e);
        int lo = 0, hi = 64;
#pragma unroll
        for (int it = 0; it < 7; it++) {
            if (lo < hi) {
                int mid = (lo + hi) >> 1;
                if (sS[mid] < a) lo = mid + 1; else hi = mid;
            }
        }
        int pos = __ldg(&gOff[dst]) + __ldg(&gRank[e]);
        gRec[pos] = make_uint2((unsigned)src | ((unsigned)lo << 20), __float_as_uint(a));
    }
}

// ---------------- CSR aggregation: no atomics, 4-deep gather pipeline ----------------
// 16 lanes per dst (one float4 chunk each), 2 dsts per warp.
__global__ void __launch_bounds__(256) edge_aggr_kernel(
    const float* __restrict__ hin, float* __restrict__ aggr, int n) {
    __shared__ float4 sU[65 * 16];
    __shared__ float4 sV[65 * 16];
    const float4* gU4 = (const float4*)gU;
    const float4* gV4 = (const float4*)gV;
    for (int i = threadIdx.x; i < 65 * 16; i += 256) { sU[i] = gU4[i]; sV[i] = gV4[i]; }
    __syncthreads();

    const int lane = threadIdx.x & 31;
    const int sub = lane >> 4;
    const int c = lane & 15;

    long long w = ((long long)blockIdx.x * 256 + threadIdx.x) >> 5;
    long long nw = ((long long)gridDim.x * 256) >> 5;
    for (long long d = w * 2 + sub; d < n; d += nw * 2) {
        int e = __ldg(&gOff[d]);
        int en = __ldg(&gOff[d + 1]);
        float4 acc = make_float4(0.f, 0.f, 0.f, 0.f);
        // 4-deep: batch record loads, then batch gathers, then math
        for (; e + 4 <= en; e += 4) {
            uint2 r0 = __ldg(&gRec[e]);
            uint2 r1 = __ldg(&gRec[e + 1]);
            uint2 r2 = __ldg(&gRec[e + 2]);
            uint2 r3 = __ldg(&gRec[e + 3]);
            float4 h0 = __ldg((const float4*)(hin + ((size_t)(r0.x & 0xFFFFFu) << 6)) + c);
            float4 h1 = __ldg((const float4*)(hin + ((size_t)(r1.x & 0xFFFFFu) << 6)) + c);
            float4 h2 = __ldg((const float4*)(hin + ((size_t)(r2.x & 0xFFFFFu) << 6)) + c);
            float4 h3 = __ldg((const float4*)(hin + ((size_t)(r3.x & 0xFFFFFu) << 6)) + c);
#define EDGE_STEP(rr, hh) do {                                          \
            float a_ = __uint_as_float(rr.y);                           \
            int li_ = (int)(rr.x >> 20);                                \
            float4 u_ = sU[li_ * 16 + c];                               \
            float4 v_ = sV[li_ * 16 + c];                               \
            acc.x += fmaxf(fmaf(a_, u_.x, v_.x + hh.x), 0.f);           \
            acc.y += fmaxf(fmaf(a_, u_.y, v_.y + hh.y), 0.f);           \
            acc.z += fmaxf(fmaf(a_, u_.z, v_.z + hh.z), 0.f);           \
            acc.w += fmaxf(fmaf(a_, u_.w, v_.w + hh.w), 0.f);           \
        } while (0)
            EDGE_STEP(r0, h0);
            EDGE_STEP(r1, h1);
            EDGE_STEP(r2, h2);
            EDGE_STEP(r3, h3);
        }
        for (; e < en; e++) {
            uint2 r0 = __ldg(&gRec[e]);
            float4 h0 = __ldg((const float4*)(hin + ((size_t)(r0.x & 0xFFFFFu) << 6)) + c);
            EDGE_STEP(r0, h0);
        }
#undef EDGE_STEP
        ((float4*)(aggr + ((size_t)d << 6)))[c] = acc;
    }
}

// ---------------- fused conv MLP: out = relu( relu(z@W1+b1) @ W2 + b2 ), z=(1+eps)x+aggr ----------------
__global__ void __launch_bounds__(128) conv_mlp_kernel(
    const float* X, const float* Ag, const float* __restrict__ epsPtr,
    const float* __restrict__ W1, const float* __restrict__ B1,
    const float* __restrict__ W2, const float* __restrict__ B2,
    float* Out, int n) {
    __shared__ __align__(16) float sW1[4096];
    __shared__ __align__(16) float sW2[4096];
    __shared__ float sB1[64], sB2[64];
    for (int i = threadIdx.x; i < 4096; i += 128) { sW1[i] = W1[i]; sW2[i] = W2[i]; }
    if (threadIdx.x < 64) { sB1[threadIdx.x] = B1[threadIdx.x]; sB2[threadIdx.x] = B2[threadIdx.x]; }
    __syncthreads();
    int r = blockIdx.x * 128 + threadIdx.x;
    if (r >= n) return;
    float ep = 1.0f + __ldg(epsPtr);

    unsigned long long acc[32];
#pragma unroll
    for (int p = 0; p < 32; p++) acc[p] = pk2(sB1[2 * p], sB1[2 * p + 1]);

    const float4* x4 = (const float4*)(X + ((size_t)r << 6));
    const float4* y4 = (const float4*)(Ag + ((size_t)r << 6));
#pragma unroll 1
    for (int jc = 0; jc < 16; jc++) {
        float4 xv = __ldg(x4 + jc), yv = __ldg(y4 + jc);
        float zz[4];
        zz[0] = fmaf(ep, xv.x, yv.x);
        zz[1] = fmaf(ep, xv.y, yv.y);
        zz[2] = fmaf(ep, xv.z, yv.z);
        zz[3] = fmaf(ep, xv.w, yv.w);
#pragma unroll
        for (int jj = 0; jj < 4; jj++) {
            unsigned long long zb = pk2(zz[jj], zz[jj]);
            const ulonglong2* wr = (const ulonglong2*)(sW1 + ((4 * jc + jj) << 6));
#pragma unroll
            for (int q = 0; q < 16; q++) {
                ulonglong2 wv = wr[q];
                acc[2 * q]     = ffma2(zb, wv.x, acc[2 * q]);
                acc[2 * q + 1] = ffma2(zb, wv.y, acc[2 * q + 1]);
            }
        }
    }

    unsigned long long acc2[32];
#pragma unroll
    for (int p = 0; p < 32; p++) acc2[p] = pk2(sB2[2 * p], sB2[2 * p + 1]);
#pragma unroll
    for (int p = 0; p < 32; p++) {
        float t0, t1;
        upk2(acc[p], t0, t1);
        t0 = fmaxf(t0, 0.f);
        t1 = fmaxf(t1, 0.f);
        unsigned long long zb0 = pk2(t0, t0);
        unsigned long long zb1 = pk2(t1, t1);
        const ulonglong2* w0 = (const ulonglong2*)(sW2 + ((2 * p) << 6));
        const ulonglong2* w1r = (const ulonglong2*)(sW2 + ((2 * p + 1) << 6));
#pragma unroll
        for (int q = 0; q < 16; q++) {
            ulonglong2 wv = w0[q];
            acc2[2 * q]     = ffma2(zb0, wv.x, acc2[2 * q]);
            acc2[2 * q + 1] = ffma2(zb0, wv.y, acc2[2 * q + 1]);
        }
#pragma unroll
        for (int q = 0; q < 16; q++) {
            ulonglong2 wv = w1r[q];
            acc2[2 * q]     = ffma2(zb1, wv.x, acc2[2 * q]);
            acc2[2 * q + 1] = ffma2(zb1, wv.y, acc2[2 * q + 1]);
        }
    }
    float4* o4 = (float4*)(Out + ((size_t)r << 6));
#pragma unroll
    for (int q = 0; q < 16; q++) {
        float a, b, cc, dd;
        upk2(acc2[2 * q], a, b);
        upk2(acc2[2 * q + 1], cc, dd);
        o4[q] = make_float4(fmaxf(a, 0.f), fmaxf(b, 0.f), fmaxf(cc, 0.f), fmaxf(dd, 0.f));
    }
}

// ---------------- classifier + fused log_softmax (H=64 -> C=40) ----------------
__global__ void __launch_bounds__(256) cls_kernel(
    const float* __restrict__ X, const float* __restrict__ W,
    const float* __restrict__ Bv, float* __restrict__ Out, int n) {
    __shared__ __align__(16) float sW[64 * 40];
    __shared__ float sB[40];
    for (int i = threadIdx.x; i < 64 * 40; i += 256) sW[i] = W[i];
    if (threadIdx.x < 40) sB[threadIdx.x] = Bv[threadIdx.x];
    __syncthreads();
    int r = blockIdx.x * 256 + threadIdx.x;
    if (r >= n) return;
    float4 acc[10];
#pragma unroll
    for (int q = 0; q < 10; q++)
        acc[q] = make_float4(sB[4 * q], sB[4 * q + 1], sB[4 * q + 2], sB[4 * q + 3]);
    const float4* x4 = (const float4*)(X + ((size_t)r << 6));
#pragma unroll 1
    for (int jc = 0; jc < 16; jc++) {
        float4 xv = __ldg(x4 + jc);
        float xs[4] = {xv.x, xv.y, xv.z, xv.w};
#pragma unroll
        for (int jj = 0; jj < 4; jj++) {
            float xj = xs[jj];
            const float4* wr = (const float4*)(sW + (4 * jc + jj) * 40);
#pragma unroll
            for (int q = 0; q < 10; q++) {
                float4 wv = wr[q];
                acc[q].x = fmaf(xj, wv.x, acc[q].x);
                acc[q].y = fmaf(xj, wv.y, acc[q].y);
                acc[q].z = fmaf(xj, wv.z, acc[q].z);
                acc[q].w = fmaf(xj, wv.w, acc[q].w);
            }
        }
    }
    float m = -3.4e38f;
#pragma unroll
    for (int q = 0; q < 10; q++)
        m = fmaxf(m, fmaxf(fmaxf(acc[q].x, acc[q].y), fmaxf(acc[q].z, acc[q].w)));
    float s = 0.f;
#pragma unroll
    for (int q = 0; q < 10; q++)
        s += expf(acc[q].x - m) + expf(acc[q].y - m) + expf(acc[q].z - m) + expf(acc[q].w - m);
    float lse = m + logf(s);
    float4* o4 = (float4*)(Out + (size_t)r * 40);
#pragma unroll
    for (int q = 0; q < 10; q++)
        o4[q] = make_float4(acc[q].x - lse, acc[q].y - lse, acc[q].z - lse, acc[q].w - lse);
}

// ---------------- launch ----------------
extern "C" void kernel_launch(void* const* d_in, const int* in_sizes, int n_in,
                              void* d_out, int out_size) {
    const float* x     = (const float*)d_in[0];
    const void*  eidx  = d_in[1];
    const float* eattr = (const float*)d_in[2];
    const float* e_w1  = (const float*)d_in[3];
    const float* e_b1  = (const float*)d_in[4];
    const float* e_w2  = (const float*)d_in[5];
    const float* e_b2  = (const float*)d_in[6];
    const float* eps1  = (const float*)d_in[7];
    const float* m1_w1 = (const float*)d_in[8];
    const float* m1_b1 = (const float*)d_in[9];
    const float* m1_w2 = (const float*)d_in[10];
    const float* m1_b2 = (const float*)d_in[11];
    const float* eps2  = (const float*)d_in[12];
    const float* m2_w1 = (const float*)d_in[13];
    const float* m2_b1 = (const float*)d_in[14];
    const float* m2_w2 = (const float*)d_in[15];
    const float* m2_b2 = (const float*)d_in[16];
    const float* lin_w = (const float*)d_in[17];
    const float* lin_b = (const float*)d_in[18];

    int N = in_sizes[0] / HD;
    long long E = in_sizes[2];
    float* out = (float*)d_out;

    void *pA, *pH;
    cudaGetSymbolAddress(&pA, gAggr);
    cudaGetSymbolAddress(&pH, gH);
    float* A = (float*)pA;
    float* H = (float*)pH;

    int nbScan = (N + 511) / 512;
    int nbMlp = (N + 127) / 128;
    int nbCls = (N + 255) / 256;

    // --- one-time preprocessing (tables + dst-sorted edge records) ---
    prep_kernel<<<17, 256>>>(e_w1, e_b1, e_w2, e_b2);
    sniff_kernel<<<1, 256>>>((const int*)eidx, E);
    zero_int_kernel<<<(N + 255) / 256, 256>>>(N);
    hist_kernel<<<1184, 256>>>(eidx, E);
    scan1_kernel<<<nbScan, 256>>>(N);
    scan2_kernel<<<1, 256>>>(nbScan);
    scan3_kernel<<<nbScan, 256>>>(N);
    scatter_kernel<<<1184, 256>>>(eidx, eattr, E);

    // --- conv1 ---
    edge_aggr_kernel<<<1184, 256>>>(x, A, N);
    conv_mlp_kernel<<<nbMlp, 128>>>(x, A, eps1, m1_w1, m1_b1, m1_w2, m1_b2, H, N);

    // --- conv2 (MLP in-place on H) ---
    edge_aggr_kernel<<<1184, 256>>>(H, A, N);
    conv_mlp_kernel<<<nbMlp, 128>>>(H, A, eps2, m2_w1, m2_b1, m2_w2, m2_b2, H, N);

    // --- classifier + log_softmax ---
    cls_kernel<<<nbCls, 256>>>(H, lin_w, lin_b, out, N);
}

// round 17
// speedup vs baseline: 1.0671x; 1.0004x over previous
#include <cuda_runtime.h>
#include <math.h>

#define HD 64
#define NMAX 100000
#define EMAX 1600000

// ---------------- device scratch (no allocations allowed) ----------------
__device__ __align__(16) float gAggr[NMAX * HD];
__device__ __align__(16) float gH[NMAX * HD];
__device__ __align__(16) float gU[65 * HD];   // piecewise-linear slope table
__device__ __align__(16) float gV[65 * HD];   // piecewise-linear offset table
__device__ float gS[HD];                      // sorted breakpoints
__device__ int gIs64;                         // edge_index dtype flag
__device__ __align__(16) uint2 gRec[EMAX];    // dst-sorted records {src|lo<<20, a}
__device__ int gRank[EMAX];                   // rank of edge within its dst segment
__device__ int gCnt[NMAX];
__device__ int gOff[NMAX + 1];
__device__ int gPart[256];

// ---------------- f32x2 packed helpers ----------------
static __device__ __forceinline__ unsigned long long pk2(float a, float b) {
    unsigned long long r;
    asm("mov.b64 %0, {%1, %2};" : "=l"(r) : "f"(a), "f"(b));
    return r;
}
static __device__ __forceinline__ void upk2(unsigned long long v, float& a, float& b) {
    asm("mov.b64 {%0, %1}, %2;" : "=f"(a), "=f"(b) : "l"(v));
}
static __device__ __forceinline__ unsigned long long ffma2(
    unsigned long long a, unsigned long long b, unsigned long long c) {
    unsigned long long d;
    asm("fma.rn.f32x2 %0, %1, %2, %3;" : "=l"(d) : "l"(a), "l"(b), "l"(c));
    return d;
}

// ---------------- prep: piecewise-linear edge-MLP tables ----------------
__global__ void prep_kernel(const float* __restrict__ w1, const float* __restrict__ b1,
                            const float* __restrict__ w2, const float* __restrict__ b2) {
    __shared__ float sw1[64], sb1[64], st[64], ss[64], stp[65];
    __shared__ float sw2[4096];
    int tid = threadIdx.x;
    if (tid < 64) { sw1[tid] = w1[tid]; sb1[tid] = b1[tid]; }
    for (int i = tid; i < 4096; i += 256) sw2[i] = w2[i];
    __syncthreads();
    if (tid < 64) {
        float w = sw1[tid], b = sb1[tid];
        st[tid] = (w != 0.0f) ? (-b / w) : __int_as_float(0x7f800000);
    }
    __syncthreads();
    if (tid < 64) {  // rank sort
        float v = st[tid];
        int rank = 0;
        for (int k = 0; k < 64; k++) {
            float u = st[k];
            rank += (u < v) || (u == v && k < tid);
        }
        ss[rank] = v;
    }
    __syncthreads();
    if (tid <= 64) {
        float lo = (tid == 0) ? -__int_as_float(0x7f800000) : ss[tid - 1];
        float hi = (tid == 64) ? __int_as_float(0x7f800000) : ss[tid];
        bool loI = !(lo > -3.0e38f);
        bool hiI = !(hi < 3.0e38f);
        float tp;
        if (loI && hiI)      tp = 0.0f;
        else if (loI)        tp = hi - 1.0f;
        else if (hiI)        tp = lo + 1.0f;
        else                 tp = 0.5f * lo + 0.5f * hi;
        stp[tid] = tp;
        if (blockIdx.x == 0 && tid < 64) gS[tid] = ss[tid];
    }
    __syncthreads();
    int idx = blockIdx.x * 256 + tid;
    if (idx < 65 * 64) {
        int i = idx >> 6, k = idx & 63;
        float a = stp[i];
        float U = 0.f, V = 0.f;
        for (int j = 0; j < 64; j++) {
            float w = sw1[j], b = sb1[j];
            if (a * w + b > 0.0f) {
                float wk = sw2[j * 64 + k];
                U = fmaf(w, wk, U);
                V = fmaf(b, wk, V);
            }
        }
        gU[idx] = U;
        gV[idx] = V + __ldg(b2 + k);
    }
}

// ---------------- sniff: int64 vs int32 edge_index ----------------
__global__ void sniff_kernel(const int* __restrict__ p, long long E) {
    __shared__ int nz;
    if (threadIdx.x == 0) nz = 0;
    __syncthreads();
    long long lim = 1024;
    if (E / 2 < lim) lim = E / 2;
    for (long long i = threadIdx.x; i < lim; i += blockDim.x)
        if (p[2 * i + 1] != 0) atomicOr(&nz, 1);
    __syncthreads();
    if (threadIdx.x == 0) gIs64 = (nz == 0) ? 1 : 0;
}

// ---------------- counting sort by dst ----------------
__global__ void zero_int_kernel(int n) {
    int i = blockIdx.x * blockDim.x + threadIdx.x;
    if (i < n) gCnt[i] = 0;
}

// histogram; atomicAdd return value = rank of this edge within its dst segment
__global__ void hist_kernel(const void* __restrict__ idxPtr, long long E) {
    const int is64 = gIs64;
    const long long* i64 = (const long long*)idxPtr;
    const int* i32 = (const int*)idxPtr;
    long long stride = (long long)gridDim.x * blockDim.x;
    for (long long e = (long long)blockIdx.x * blockDim.x + threadIdx.x; e < E; e += stride) {
        int dst = is64 ? (int)__ldg(&i64[E + e]) : __ldg(&i32[E + e]);
        gRank[e] = atomicAdd(&gCnt[dst], 1);
    }
}

__global__ void scan1_kernel(int n) {
    __shared__ int sd[256];
    int base = blockIdx.x * 512;
    int i0 = base + threadIdx.x, i1 = base + 256 + threadIdx.x;
    int c = 0;
    if (i0 < n) c += gCnt[i0];
    if (i1 < n) c += gCnt[i1];
    sd[threadIdx.x] = c;
    __syncthreads();
    for (int s = 128; s > 0; s >>= 1) {
        if (threadIdx.x < s) sd[threadIdx.x] += sd[threadIdx.x + s];
        __syncthreads();
    }
    if (threadIdx.x == 0) gPart[blockIdx.x] = sd[0];
}

__global__ void scan2_kernel(int nb) {
    __shared__ int sd[256];
    int tid = threadIdx.x;
    int v = (tid < nb) ? gPart[tid] : 0;
    sd[tid] = v;
    __syncthreads();
    for (int ofs = 1; ofs < 256; ofs <<= 1) {
        int add = 0;
        if (tid >= ofs) add = sd[tid - ofs];
        __syncthreads();
        sd[tid] += add;
        __syncthreads();
    }
    if (tid < nb) gPart[tid] = sd[tid] - v;  // exclusive
}

__global__ void scan3_kernel(int n) {
    __shared__ int sd[256];
    int base = blockIdx.x * 512;
    int i0 = base + 2 * threadIdx.x, i1 = i0 + 1;
    int c0 = (i0 < n) ? gCnt[i0] : 0;
    int c1 = (i1 < n) ? gCnt[i1] : 0;
    int tsum = c0 + c1;
    sd[threadIdx.x] = tsum;
    __syncthreads();
    for (int ofs = 1; ofs < 256; ofs <<= 1) {
        int add = 0;
        if (threadIdx.x >= ofs) add = sd[threadIdx.x - ofs];
        __syncthreads();
        sd[threadIdx.x] += add;
        __syncthreads();
    }
    int ex = gPart[blockIdx.x] + sd[threadIdx.x] - tsum;
    if (i0 < n) gOff[i0] = ex;
    if (i1 < n) gOff[i1] = ex + c0;
    if (i0 == n - 1) gOff[n] = ex + c0;
    if (i1 == n - 1) gOff[n] = ex + c0 + c1;
}

// atomic-free scatter: pos = gOff[dst] + precomputed rank; 8-byte packed record
__global__ void scatter_kernel(const void* __restrict__ idxPtr,
                               const float* __restrict__ attr, long long E) {
    __shared__ float sS[64];
    if (threadIdx.x < 64) sS[threadIdx.x] = gS[threadIdx.x];
    __syncthreads();
    const int is64 = gIs64;
    const long long* i64 = (const long long*)idxPtr;
    const int* i32 = (const int*)idxPtr;
    long long stride = (long long)gridDim.x * blockDim.x;
    for (long long e = (long long)blockIdx.x * blockDim.x + threadIdx.x; e < E; e += stride) {
        int src, dst;
        if (is64) { src = (int)__ldg(&i64[e]); dst = (int)__ldg(&i64[E + e]); }
        else      { src = __ldg(&i32[e]);      dst = __ldg(&i32[E + e]); }
        float a = __ldg(attr + e);
        int lo = 0, hi = 64;
#pragma unroll
        for (int it = 0; it < 7; it++) {
            if (lo < hi) {
                int mid = (lo + hi) >> 1;
                if (sS[mid] < a) lo = mid + 1; else hi = mid;
            }
        }
        int pos = __ldg(&gOff[dst]) + __ldg(&gRank[e]);
        gRec[pos] = make_uint2((unsigned)src | ((unsigned)lo << 20), __float_as_uint(a));
    }
}

// ---------------- CSR aggregation: no atomics, 4-deep gather pipeline ----------------
// 16 lanes per dst (one float4 chunk each), 2 dsts per warp.
__global__ void __launch_bounds__(256) edge_aggr_kernel(
    const float* __restrict__ hin, float* __restrict__ aggr, int n) {
    __shared__ float4 sU[65 * 16];
    __shared__ float4 sV[65 * 16];
    const float4* gU4 = (const float4*)gU;
    const float4* gV4 = (const float4*)gV;
    for (int i = threadIdx.x; i < 65 * 16; i += 256) { sU[i] = gU4[i]; sV[i] = gV4[i]; }
    __syncthreads();

    const int lane = threadIdx.x & 31;
    const int sub = lane >> 4;
    const int c = lane & 15;

    long long w = ((long long)blockIdx.x * 256 + threadIdx.x) >> 5;
    long long nw = ((long long)gridDim.x * 256) >> 5;
    for (long long d = w * 2 + sub; d < n; d += nw * 2) {
        int e = __ldg(&gOff[d]);
        int en = __ldg(&gOff[d + 1]);
        float4 acc = make_float4(0.f, 0.f, 0.f, 0.f);
        // 4-deep: batch record loads, then batch gathers, then math
        for (; e + 4 <= en; e += 4) {
            uint2 r0 = __ldg(&gRec[e]);
            uint2 r1 = __ldg(&gRec[e + 1]);
            uint2 r2 = __ldg(&gRec[e + 2]);
            uint2 r3 = __ldg(&gRec[e + 3]);
            float4 h0 = __ldg((const float4*)(hin + ((size_t)(r0.x & 0xFFFFFu) << 6)) + c);
            float4 h1 = __ldg((const float4*)(hin + ((size_t)(r1.x & 0xFFFFFu) << 6)) + c);
            float4 h2 = __ldg((const float4*)(hin + ((size_t)(r2.x & 0xFFFFFu) << 6)) + c);
            float4 h3 = __ldg((const float4*)(hin + ((size_t)(r3.x & 0xFFFFFu) << 6)) + c);
#define EDGE_STEP(rr, hh) do {                                          \
            float a_ = __uint_as_float(rr.y);                           \
            int li_ = (int)(rr.x >> 20);                                \
            float4 u_ = sU[li_ * 16 + c];                               \
            float4 v_ = sV[li_ * 16 + c];                               \
            acc.x += fmaxf(fmaf(a_, u_.x, v_.x + hh.x), 0.f);           \
            acc.y += fmaxf(fmaf(a_, u_.y, v_.y + hh.y), 0.f);           \
            acc.z += fmaxf(fmaf(a_, u_.z, v_.z + hh.z), 0.f);           \
            acc.w += fmaxf(fmaf(a_, u_.w, v_.w + hh.w), 0.f);           \
        } while (0)
            EDGE_STEP(r0, h0);
            EDGE_STEP(r1, h1);
            EDGE_STEP(r2, h2);
            EDGE_STEP(r3, h3);
        }
        for (; e < en; e++) {
            uint2 r0 = __ldg(&gRec[e]);
            float4 h0 = __ldg((const float4*)(hin + ((size_t)(r0.x & 0xFFFFFu) << 6)) + c);
            EDGE_STEP(r0, h0);
        }
#undef EDGE_STEP
        ((float4*)(aggr + ((size_t)d << 6)))[c] = acc;
    }
}

// ---------------- fused conv MLP: out = relu( relu(z@W1+b1) @ W2 + b2 ), z=(1+eps)x+aggr ----------------
__global__ void __launch_bounds__(128) conv_mlp_kernel(
    const float* X, const float* Ag, const float* __restrict__ epsPtr,
    const float* __restrict__ W1, const float* __restrict__ B1,
    const float* __restrict__ W2, const float* __restrict__ B2,
    float* Out, int n) {
    __shared__ __align__(16) float sW1[4096];
    __shared__ __align__(16) float sW2[4096];
    __shared__ float sB1[64], sB2[64];
    for (int i = threadIdx.x; i < 4096; i += 128) { sW1[i] = W1[i]; sW2[i] = W2[i]; }
    if (threadIdx.x < 64) { sB1[threadIdx.x] = B1[threadIdx.x]; sB2[threadIdx.x] = B2[threadIdx.x]; }
    __syncthreads();
    int r = blockIdx.x * 128 + threadIdx.x;
    if (r >= n) return;
    float ep = 1.0f + __ldg(epsPtr);

    unsigned long long acc[32];
#pragma unroll
    for (int p = 0; p < 32; p++) acc[p] = pk2(sB1[2 * p], sB1[2 * p + 1]);

    const float4* x4 = (const float4*)(X + ((size_t)r << 6));
    const float4* y4 = (const float4*)(Ag + ((size_t)r << 6));
#pragma unroll 1
    for (int jc = 0; jc < 16; jc++) {
        float4 xv = __ldg(x4 + jc), yv = __ldg(y4 + jc);
        float zz[4];
        zz[0] = fmaf(ep, xv.x, yv.x);
        zz[1] = fmaf(ep, xv.y, yv.y);
        zz[2] = fmaf(ep, xv.z, yv.z);
        zz[3] = fmaf(ep, xv.w, yv.w);
#pragma unroll
        for (int jj = 0; jj < 4; jj++) {
            unsigned long long zb = pk2(zz[jj], zz[jj]);
            const ulonglong2* wr = (const ulonglong2*)(sW1 + ((4 * jc + jj) << 6));
#pragma unroll
            for (int q = 0; q < 16; q++) {
                ulonglong2 wv = wr[q];
                acc[2 * q]     = ffma2(zb, wv.x, acc[2 * q]);
                acc[2 * q + 1] = ffma2(zb, wv.y, acc[2 * q + 1]);
            }
        }
    }

    unsigned long long acc2[32];
#pragma unroll
    for (int p = 0; p < 32; p++) acc2[p] = pk2(sB2[2 * p], sB2[2 * p + 1]);
#pragma unroll
    for (int p = 0; p < 32; p++) {
        float t0, t1;
        upk2(acc[p], t0, t1);
        t0 = fmaxf(t0, 0.f);
        t1 = fmaxf(t1, 0.f);
        unsigned long long zb0 = pk2(t0, t0);
        unsigned long long zb1 = pk2(t1, t1);
        const ulonglong2* w0 = (const ulonglong2*)(sW2 + ((2 * p) << 6));
        const ulonglong2* w1r = (const ulonglong2*)(sW2 + ((2 * p + 1) << 6));
#pragma unroll
        for (int q = 0; q < 16; q++) {
            ulonglong2 wv = w0[q];
            acc2[2 * q]     = ffma2(zb0, wv.x, acc2[2 * q]);
            acc2[2 * q + 1] = ffma2(zb0, wv.y, acc2[2 * q + 1]);
        }
#pragma unroll
        for (int q = 0; q < 16; q++) {
            ulonglong2 wv = w1r[q];
            acc2[2 * q]     = ffma2(zb1, wv.x, acc2[2 * q]);
            acc2[2 * q + 1] = ffma2(zb1, wv.y, acc2[2 * q + 1]);
        }
    }
    float4* o4 = (float4*)(Out + ((size_t)r << 6));
#pragma unroll
    for (int q = 0; q < 16; q++) {
        float a, b, cc, dd;
        upk2(acc2[2 * q], a, b);
        upk2(acc2[2 * q + 1], cc, dd);
        o4[q] = make_float4(fmaxf(a, 0.f), fmaxf(b, 0.f), fmaxf(cc, 0.f), fmaxf(dd, 0.f));
    }
}

// ---------------- classifier + fused log_softmax (H=64 -> C=40) ----------------
__global__ void __launch_bounds__(256) cls_kernel(
    const float* __restrict__ X, const float* __restrict__ W,
    const float* __restrict__ Bv, float* __restrict__ Out, int n) {
    __shared__ __align__(16) float sW[64 * 40];
    __shared__ float sB[40];
    for (int i = threadIdx.x; i < 64 * 40; i += 256) sW[i] = W[i];
    if (threadIdx.x < 40) sB[threadIdx.x] = Bv[threadIdx.x];
    __syncthreads();
    int r = blockIdx.x * 256 + threadIdx.x;
    if (r >= n) return;
    float4 acc[10];
#pragma unroll
    for (int q = 0; q < 10; q++)
        acc[q] = make_float4(sB[4 * q], sB[4 * q + 1], sB[4 * q + 2], sB[4 * q + 3]);
    const float4* x4 = (const float4*)(X + ((size_t)r << 6));
#pragma unroll 1
    for (int jc = 0; jc < 16; jc++) {
        float4 xv = __ldg(x4 + jc);
        float xs[4] = {xv.x, xv.y, xv.z, xv.w};
#pragma unroll
        for (int jj = 0; jj < 4; jj++) {
            float xj = xs[jj];
            const float4* wr = (const float4*)(sW + (4 * jc + jj) * 40);
#pragma unroll
            for (int q = 0; q < 10; q++) {
                float4 wv = wr[q];
                acc[q].x = fmaf(xj, wv.x, acc[q].x);
                acc[q].y = fmaf(xj, wv.y, acc[q].y);
                acc[q].z = fmaf(xj, wv.z, acc[q].z);
                acc[q].w = fmaf(xj, wv.w, acc[q].w);
            }
        }
    }
    float m = -3.4e38f;
#pragma unroll
    for (int q = 0; q < 10; q++)
        m = fmaxf(m, fmaxf(fmaxf(acc[q].x, acc[q].y), fmaxf(acc[q].z, acc[q].w)));
    float s = 0.f;
#pragma unroll
    for (int q = 0; q < 10; q++)
        s += expf(acc[q].x - m) + expf(acc[q].y - m) + expf(acc[q].z - m) + expf(acc[q].w - m);
    float lse = m + logf(s);
    float4* o4 = (float4*)(Out + (size_t)r * 40);
#pragma unroll
    for (int q = 0; q < 10; q++)
        o4[q] = make_float4(acc[q].x - lse, acc[q].y - lse, acc[q].z - lse, acc[q].w - lse);
}

// ---------------- launch ----------------
extern "C" void kernel_launch(void* const* d_in, const int* in_sizes, int n_in,
                              void* d_out, int out_size) {
    const float* x     = (const float*)d_in[0];
    const void*  eidx  = d_in[1];
    const float* eattr = (const float*)d_in[2];
    const float* e_w1  = (const float*)d_in[3];
    const float* e_b1  = (const float*)d_in[4];
    const float* e_w2  = (const float*)d_in[5];
    const float* e_b2  = (const float*)d_in[6];
    const float* eps1  = (const float*)d_in[7];
    const float* m1_w1 = (const float*)d_in[8];
    const float* m1_b1 = (const float*)d_in[9];
    const float* m1_w2 = (const float*)d_in[10];
    const float* m1_b2 = (const float*)d_in[11];
    const float* eps2  = (const float*)d_in[12];
    const float* m2_w1 = (const float*)d_in[13];
    const float* m2_b1 = (const float*)d_in[14];
    const float* m2_w2 = (const float*)d_in[15];
    const float* m2_b2 = (const float*)d_in[16];
    const float* lin_w = (const float*)d_in[17];
    const float* lin_b = (const float*)d_in[18];

    int N = in_sizes[0] / HD;
    long long E = in_sizes[2];
    float* out = (float*)d_out;

    void *pA, *pH;
    cudaGetSymbolAddress(&pA, gAggr);
    cudaGetSymbolAddress(&pH, gH);
    float* A = (float*)pA;
    float* H = (float*)pH;

    int nbScan = (N + 511) / 512;
    int nbMlp = (N + 127) / 128;
    int nbCls = (N + 255) / 256;

    // --- one-time preprocessing (tables + dst-sorted edge records) ---
    prep_kernel<<<17, 256>>>(e_w1, e_b1, e_w2, e_b2);
    sniff_kernel<<<1, 256>>>((const int*)eidx, E);
    zero_int_kernel<<<(N + 255) / 256, 256>>>(N);
    hist_kernel<<<1184, 256>>>(eidx, E);
    scan1_kernel<<<nbScan, 256>>>(N);
    scan2_kernel<<<1, 256>>>(nbScan);
    scan3_kernel<<<nbScan, 256>>>(N);
    scatter_kernel<<<1184, 256>>>(eidx, eattr, E);

    // --- conv1 ---
    edge_aggr_kernel<<<1184, 256>>>(x, A, N);
    conv_mlp_kernel<<<nbMlp, 128>>>(x, A, eps1, m1_w1, m1_b1, m1_w2, m1_b2, H, N);

    // --- conv2 (MLP in-place on H) ---
    edge_aggr_kernel<<<1184, 256>>>(H, A, N);
    conv_mlp_kernel<<<nbMlp, 128>>>(H, A, eps2, m2_w1, m2_b1, m2_w2, m2_b2, H, N);

    // --- classifier + log_softmax ---
    cls_kernel<<<nbCls, 256>>>(H, lin_w, lin_b, out, N);
}